// round 7
// baseline (speedup 1.0000x reference)
#include <cuda_runtime.h>
#include <math.h>

#define BN 4
#define CCH 21
#define HH 96
#define WW 96
#define NN (HH*WW)          // 9216
#define NEH (HH*(WW-1))     // 9120
#define NEV ((HH-1)*WW)     // 9120
#define NE  (NEH+NEV)       // 18240
#define NTREE 8             // s = b*2 + t, t=0 low, t=1 high
#define NCHUNK 32
#define CHSZ  16            // 512 / NCHUNK
#define ROOT  (48*WW + 48)
#define MAXCH 8192          // max chains (= #leaves <= ~3/4 NN)

// ---------------- scratch ----------------
__device__ double g_ws[NTREE*NE];
__device__ unsigned long long g_key[NTREE*NE];
__device__ double g_part[BN*NCHUNK*NE];
__device__ int    g_adj[NTREE*NN*4];
__device__ int    g_ord[NTREE*NN];     // node at BFS position
__device__ int    g_pp[NTREE*NN];      // parent BFS position
__device__ int    g_loff[NTREE*(NN+4)];
__device__ int    g_nlev[NTREE];
__device__ float  g_w[NTREE*NN];       // weight, BFS-position-indexed
// HLD outputs (chain-order indexed)
__device__ int    g_cnode[NTREE*NN];   // node id at chain position
__device__ float  g_cw[NTREE*NN];      // parent-edge weight at chain position
__device__ int    g_crec[NTREE*MAXCH]; // (start<<14)|len
__device__ int    g_cparc[NTREE*MAXCH];// chain-order index of head's parent
__device__ int    g_clvloff[NTREE*34]; // chain offsets per chain-level
__device__ int    g_nclvl[NTREE];
__device__ float  g_prob[BN*CCH*NN];
__device__ float  g_S[BN*(CCH+1)*NN];
__device__ float  g_S2[BN*(CCH+1)*NN];
__device__ double g_acc[2];

__device__ __forceinline__ void edge_nodes(int e, int &a, int &b) {
    if (e < NEH) { int r = e / (WW-1); int c = e - r*(WW-1); a = r*WW + c; b = a + 1; }
    else         { a = e - NEH; b = a + WW; }
}

__device__ __forceinline__ unsigned long long pack_key(double w, int e) {
    unsigned long long kb = (unsigned long long)__double_as_longlong(w);
    return (kb & ~32767ull) | (unsigned long long)e;
}

__device__ __forceinline__ void two_sum(float a, float b, float &s, float &e) {
    s = __fadd_rn(a, b);
    float bp = __fsub_rn(s, a);
    e = __fadd_rn(__fsub_rn(a, __fsub_rn(s, bp)), __fsub_rn(b, bp));
}

// ---------------- kernels ----------------
__global__ void k_sigmoid(const float* __restrict__ preds) {
    int i = blockIdx.x*blockDim.x + threadIdx.x;
    if (i < 2) g_acc[i] = 0.0;
    if (i < BN*CCH*NN) g_prob[i] = 1.0f/(1.0f + expf(-preds[i]));
}

// df64 squared distance on the fp32 pipe; per-chunk partials
__global__ void k_ew_high(const float* __restrict__ hf) {
    int idx = blockIdx.x*blockDim.x + threadIdx.x;
    if (idx >= BN*NCHUNK*NE) return;
    int b = idx / (NCHUNK*NE);
    int r = idx - b*(NCHUNK*NE);
    int ch = r / NE, e = r - ch*NE;
    int a, bb; edge_nodes(e, a, bb);
    const float* f = hf + b*512*NN + ch*CHSZ*NN;
    float sh = 0.0f, sl = 0.0f;
    #pragma unroll
    for (int c = 0; c < CHSZ; c++) {
        float av = f[c*NN+a], bv = f[c*NN+bb];
        float dh, dl; two_sum(av, -bv, dh, dl);
        float p  = __fmul_rn(dh, dh);
        float pe = __fmaf_rn(dh, dh, -p);
        pe = __fmaf_rn(__fmul_rn(2.0f, dh), dl, pe);
        float t, er; two_sum(sh, p, t, er);
        sl = __fadd_rn(sl, __fadd_rn(er, pe));
        sh = t;
    }
    g_part[(b*NCHUNK + ch)*NE + e] = (double)sh + (double)sl;
}

// low-tree edge weights (f64) + fixed-order reduction of high-tree partials
__global__ void k_ew_red(const float* __restrict__ lf) {
    int idx = blockIdx.x*blockDim.x + threadIdx.x;
    if (idx >= BN*NE) return;
    int b = idx / NE, e = idx - b*NE;
    int a, bb; edge_nodes(e, a, bb);
    const float* f = lf + b*3*NN;
    double accl = 0.0;
    #pragma unroll
    for (int c = 0; c < 3; c++) {
        double d = (double)f[c*NN+a] - (double)f[c*NN+bb];
        accl += d*d;
    }
    g_ws[(b*2)*NE + e] = accl;
    g_key[(b*2)*NE + e] = pack_key(accl, e);
    double acc = 0.0;
    #pragma unroll 8
    for (int ch = 0; ch < NCHUNK; ch++) acc += g_part[(b*NCHUNK + ch)*NE + e];
    g_ws[(b*2+1)*NE + e] = acc;
    g_key[(b*2+1)*NE + e] = pack_key(acc, e);
}

// Parallel Boruvka, one block per tree.
__global__ void __launch_bounds__(1024) k_boruvka() {
    extern __shared__ unsigned long long sh_u[];
    unsigned long long* minw = sh_u;       // NN
    int* parent = (int*)(minw + NN);       // NN
    int* hook   = parent + NN;             // NN
    int* deg    = hook + NN;               // NN
    __shared__ int total;
    int s = blockIdx.x;
    const unsigned long long* key = g_key + s*NE;
    int* adj = g_adj + s*NN*4;
    for (int i = threadIdx.x; i < NN; i += blockDim.x) { parent[i] = i; deg[i] = 0; }
    for (int i = threadIdx.x; i < NN*4; i += blockDim.x) adj[i] = -1;
    if (threadIdx.x == 0) total = 0;
    __syncthreads();
    for (int round = 0; round < 24; round++) {
        for (int i = threadIdx.x; i < NN; i += blockDim.x) {
            minw[i] = 0xFFFFFFFFFFFFFFFFull; hook[i] = -1;
        }
        __syncthreads();
        for (int e = threadIdx.x; e < NE; e += blockDim.x) {
            int a, b; edge_nodes(e, a, b);
            int ra = parent[a], rb = parent[b];
            if (ra != rb) {
                unsigned long long k = key[e];
                if (k < minw[ra]) atomicMin(&minw[ra], k);
                if (k < minw[rb]) atomicMin(&minw[rb], k);
            }
        }
        __syncthreads();
        for (int i = threadIdx.x; i < NN; i += blockDim.x) {
            unsigned long long mk = minw[i];
            if (parent[i] == i && mk != 0xFFFFFFFFFFFFFFFFull) {
                int e = (int)(mk & 32767ull);
                int a, b; edge_nodes(e, a, b);
                int ra = parent[a], rb = parent[b];
                int other = (ra == i) ? rb : ra;
                bool mutual = (minw[other] == mk);
                if (!mutual || i < other) {
                    int da = atomicAdd(&deg[a], 1); adj[a*4+da] = b;
                    int db = atomicAdd(&deg[b], 1); adj[b*4+db] = a;
                    atomicAdd(&total, 1);
                    hook[i] = other;
                }
            }
        }
        __syncthreads();
        for (int i = threadIdx.x; i < NN; i += blockDim.x) {
            int t = hook[i];
            if (t >= 0) parent[i] = t;
        }
        __syncthreads();
        for (;;) {
            int any = 0;
            for (int i = threadIdx.x; i < NN; i += blockDim.x) {
                int p = parent[i], gp = parent[p];
                if (p != gp) { parent[i] = gp; any = 1; }
            }
            if (!__syncthreads_or(any)) break;
        }
        if (total >= NN-1) break;
    }
}

// Single-warp BFS from ROOT. Emits order, parent positions, level offsets, weights.
__global__ void __launch_bounds__(256) k_bfs() {
    extern __shared__ int sh[];
    int* adj_s = sh;            // NN*4
    int* ord   = adj_s + NN*4;  // NN
    int* pp    = ord + NN;      // NN
    int* cnts  = pp + NN;       // 64
    int s = blockIdx.x;
    const int* adj = g_adj + s*NN*4;
    int* loff = g_loff + s*(NN+4);
    for (int i = threadIdx.x; i < NN*4; i += blockDim.x) adj_s[i] = adj[i];
    for (int i = threadIdx.x; i < 64; i += blockDim.x) cnts[i] = 0;
    if (threadIdx.x == 0) { ord[0] = ROOT; pp[0] = 0; loff[0] = 0; loff[1] = 1; }
    __syncthreads();
    if (threadIdx.x < 32) {
        int lane = threadIdx.x;
        int cur = 0, curEnd = 1, lvl = 0;
        for (;;) {
            int slot = lvl & 63;
            for (int q = cur + lane; q < curEnd; q += 32) {
                int u = ord[q];
                int pu = (q == 0) ? -1 : ord[pp[q]];
                #pragma unroll
                for (int j = 0; j < 4; j++) {
                    int v = adj_s[u*4 + j];
                    if (v >= 0 && v != pu) {
                        int pos = atomicAdd(&cnts[slot], 1);
                        ord[curEnd + pos] = v;
                        pp[curEnd + pos] = q;
                    }
                }
            }
            __syncwarp();
            int c = cnts[slot];
            __syncwarp();
            if (lane == 0) cnts[slot] = 0;
            if (c == 0) break;
            lvl++;
            if (lane == 0) loff[lvl+1] = curEnd + c;
            cur = curEnd; curEnd += c;
        }
        if (lane == 0) g_nlev[s] = lvl + 1;
    }
    __syncthreads();
    float sig = (s & 1) ? 1.0f : 0.02f;
    for (int k = threadIdx.x; k < NN; k += blockDim.x) {
        g_ord[s*NN + k] = ord[k];
        g_pp[s*NN + k]  = pp[k];
        if (k == 0) { g_w[s*NN] = 0.0f; continue; }
        int v = ord[k];
        int u = ord[pp[k]];
        int e;
        if      (u == v-1)  { int r2 = v/WW, c2 = v%WW; e = r2*(WW-1) + (c2-1); }
        else if (u == v+1)  { int r2 = v/WW, c2 = v%WW; e = r2*(WW-1) + c2; }
        else if (u == v-WW) { e = NEH + (v-WW); }
        else                { e = NEH + v; }
        g_w[s*NN + k] = expf(-(float)g_ws[s*NE + e] / sig);
    }
}

// Heavy-path decomposition, one block per tree.
__global__ void __launch_bounds__(512) k_hld() {
    extern __shared__ int shi[];
    int* pp    = shi;            // NN
    int* ord   = pp + NN;        // NN
    int* hv    = ord + NN;       // NN  heavy child: (size<<14)|pos, -1 = none
    int* size_ = hv + NN;        // NN  subtree size, later chain len at heads
    int* clev  = size_ + NN;     // NN  chain level, later chain index at heads
    int* buf   = clev + NN;      // NN+4: loff, later cpos
    __shared__ int cntN[32], cntC[32], offN[33], offC[33], fillN[32], fillC[32];
    int s = blockIdx.x;
    int tid = threadIdx.x;
    int nl = g_nlev[s];
    for (int i = tid; i < NN; i += 512) {
        pp[i] = g_pp[s*NN+i];
        ord[i] = g_ord[s*NN+i];
        hv[i] = -1;
        size_[i] = 1;
    }
    for (int i = tid; i <= nl; i += 512) buf[i] = g_loff[s*(NN+4)+i];
    if (tid < 32) { cntN[tid]=0; cntC[tid]=0; fillN[tid]=0; fillC[tid]=0; }
    __syncthreads();
    // subtree sizes (leaves -> root)
    for (int d = nl-1; d >= 1; --d) {
        int s0 = buf[d], c2 = buf[d+1]-s0;
        if (c2 <= 32) {
            if (tid < 32) {
                if (tid < c2) { int k = s0+tid; atomicAdd(&size_[pp[k]], size_[k]); }
                __syncwarp();
            }
        } else {
            __syncthreads();
            for (int k = s0+tid; k < s0+c2; k += 512) atomicAdd(&size_[pp[k]], size_[k]);
            __syncthreads();
        }
    }
    __syncthreads();
    // heavy child per node
    for (int k = 1 + tid; k < NN; k += 512)
        atomicMax(&hv[pp[k]], (size_[k] << 14) | k);
    __syncthreads();
    // chain level (root -> leaves): +1 crossing each light edge
    if (tid == 0) clev[0] = 0;
    __syncthreads();
    for (int d = 1; d < nl; ++d) {
        int s0 = buf[d], c2 = buf[d+1]-s0;
        if (c2 <= 32) {
            if (tid < 32) {
                if (tid < c2) {
                    int k = s0+tid;
                    int p = pp[k];
                    clev[k] = clev[p] + (((hv[p] & 16383) != k) ? 1 : 0);
                }
                __syncwarp();
            }
        } else {
            __syncthreads();
            for (int k = s0+tid; k < s0+c2; k += 512) {
                int p = pp[k];
                clev[k] = clev[p] + (((hv[p] & 16383) != k) ? 1 : 0);
            }
            __syncthreads();
        }
    }
    __syncthreads();
    // count chains/nodes per chain-level
    for (int k = tid; k < NN; k += 512) {
        bool head = (k == 0) || ((hv[pp[k]] & 16383) != k);
        if (head) {
            int len = 1, j = k;
            while (hv[j] >= 0) { j = hv[j] & 16383; len++; }
            size_[k] = len;
            int lv = clev[k];
            atomicAdd(&cntN[lv], len);
            atomicAdd(&cntC[lv], 1);
        }
    }
    __syncthreads();
    if (tid == 0) {
        int on = 0, oc = 0, nlv = 0;
        for (int l = 0; l < 32; ++l) {
            offN[l] = on; offC[l] = oc;
            on += cntN[l]; oc += cntC[l];
            if (cntC[l] > 0) nlv = l + 1;
        }
        offN[32] = on; offC[32] = oc;
        g_nclvl[s] = nlv;
        for (int l = 0; l <= nlv; ++l) g_clvloff[s*34 + l] = offC[l];
    }
    __syncthreads();
    // place chains; write cnode/cw; record cpos (buf) and chain index (clev)
    for (int k = tid; k < NN; k += 512) {
        bool head = (k == 0) || ((hv[pp[k]] & 16383) != k);
        if (head) {
            int lv  = clev[k];
            int len = size_[k];
            int cs  = offN[lv] + atomicAdd(&fillN[lv], len);
            int ci  = offC[lv] + atomicAdd(&fillC[lv], 1);
            g_crec[s*MAXCH + ci] = (cs << 14) | len;
            clev[k] = ci;
            int j = k;
            for (int i2 = 0; i2 < len; ++i2) {
                buf[j] = cs + i2;
                g_cnode[s*NN + cs + i2] = ord[j];
                g_cw[s*NN + cs + i2] = g_w[s*NN + j];
                if (hv[j] >= 0) j = hv[j] & 16383;
            }
        }
    }
    __syncthreads();
    // chain parent links (chain-order index of head's parent)
    for (int k = tid; k < NN; k += 512) {
        bool head = (k == 0) || ((hv[pp[k]] & 16383) != k);
        if (head) {
            int ci = clev[k];
            g_cparc[s*MAXCH + ci] = (k == 0) ? 0 : buf[pp[k]];
        }
    }
}

// Tree DP via HLD + warp segmented affine scans. One block per (batch, channel).
__global__ void __launch_bounds__(256) k_filter(int t, int srcsel, int dst) {
    extern __shared__ float shf[];
    float* val = shf;                  // NN (A, overwritten with A')
    float* aw  = val + NN;             // NN parent-edge weight
    float* S   = aw + NN;              // NN
    int* cnode = (int*)(S + NN);       // NN
    int* crec  = cnode + NN;           // MAXCH
    int* cpar  = crec + MAXCH;         // MAXCH
    __shared__ int lvloffC[34];
    __shared__ int sh_nclvl;
    int b = blockIdx.x, c = blockIdx.y;
    int s = b*2 + t;
    int tid = threadIdx.x;
    if (tid == 0) sh_nclvl = g_nclvl[s];
    __syncthreads();
    int nclvl = sh_nclvl;
    if (tid <= nclvl) lvloffC[tid] = g_clvloff[s*34 + tid];
    __syncthreads();
    int nch = lvloffC[nclvl];
    for (int i = tid; i < NN; i += 256) {
        cnode[i] = g_cnode[s*NN + i];
        aw[i]    = g_cw[s*NN + i];
    }
    for (int i = tid; i < nch; i += 256) {
        crec[i] = g_crec[s*MAXCH + i];
        cpar[i] = g_cparc[s*MAXCH + i];
    }
    __syncthreads();
    const float* s1c = g_S + (b*(CCH+1) + c)*NN;
    const float* s1n = g_S + (b*(CCH+1) + CCH)*NN;
    for (int i = tid; i < NN; i += 256) {
        int node = cnode[i];
        float v;
        if (c == CCH)         v = 1.0f;
        else if (srcsel == 0) v = g_prob[(b*CCH + c)*NN + node];
        else                  v = s1c[node] / s1n[node];
        val[i] = v;
    }
    __syncthreads();
    int wid2 = tid >> 5, lane = tid & 31;
    // ---- up-sweep: chain-levels deepest -> root ----
    for (int L = nclvl - 1; L >= 0; --L) {
        for (int ci = lvloffC[L] + wid2; ci < lvloffC[L+1]; ci += 8) {
            int rec = crec[ci];
            int cs = rec >> 14, len = rec & 16383;
            int nt = (len + 31) >> 5;
            float carry = 0.f;
            for (int tt = nt - 1; tt >= 0; --tt) {
                int off0 = tt*32 + lane;
                bool valid = off0 < len;
                int j = cs + (valid ? off0 : 0);
                float p, q;
                if (valid) { q = val[j]; p = (off0 + 1 < len) ? aw[j+1] : 0.f; }
                else       { q = 0.f; p = 1.f; }
                #pragma unroll
                for (int o = 1; o < 32; o <<= 1) {
                    float P = __shfl_down_sync(0xffffffffu, p, o);
                    float Q = __shfl_down_sync(0xffffffffu, q, o);
                    if (lane + o < 32) { q = __fmaf_rn(p, Q, q); p *= P; }
                }
                float A = __fmaf_rn(p, carry, q);
                if (valid) val[j] = A;
                carry = __shfl_sync(0xffffffffu, A, 0);
            }
            if (lane == 0 && L > 0)
                atomicAdd(&val[cpar[ci]], aw[cs] * carry);  // carry == A'[head]
        }
        __syncthreads();
    }
    // ---- down-sweep: root -> deepest ----
    for (int L = 0; L < nclvl; ++L) {
        for (int ci = lvloffC[L] + wid2; ci < lvloffC[L+1]; ci += 8) {
            int rec = crec[ci];
            int cs = rec >> 14, len = rec & 16383;
            int nt = (len + 31) >> 5;
            float carry = (cs == 0) ? 0.f : S[cpar[ci]];
            for (int tt = 0; tt < nt; ++tt) {
                int off0 = tt*32 + lane;
                bool valid = off0 < len;
                int j = cs + (valid ? off0 : 0);
                float p, q;
                if (valid) {
                    float a = aw[j], f = val[j];
                    p = a;
                    q = f - a*a*f;
                } else { p = 1.f; q = 0.f; }
                #pragma unroll
                for (int o = 1; o < 32; o <<= 1) {
                    float P = __shfl_up_sync(0xffffffffu, p, o);
                    float Q = __shfl_up_sync(0xffffffffu, q, o);
                    if (lane >= o) { q = __fmaf_rn(p, Q, q); p *= P; }
                }
                float Sv = __fmaf_rn(p, carry, q);
                if (valid) S[j] = Sv;
                carry = __shfl_sync(0xffffffffu, Sv, 31);
            }
        }
        __syncthreads();
    }
    float* outS = ((dst == 0) ? g_S : g_S2) + (b*(CCH+1) + c)*NN;
    for (int i = tid; i < NN; i += 256) outS[cnode[i]] = S[i];
}

__global__ void k_loss(const float* __restrict__ roi) {
    __shared__ double sl[256], sn[256];
    int idx = blockIdx.x*blockDim.x + threadIdx.x;
    double l = 0.0, n = 0.0;
    if (idx < BN*NN) {
        int b = idx / NN, i = idx - b*NN;
        int h = i / WW, w = i - h*WW;
        float r = roi[b*(2*HH)*(2*WW) + (2*h)*(2*WW) + 2*w];
        n = (double)r;
        if (r != 0.0f) {
            float nrm = g_S2[(b*(CCH+1) + CCH)*NN + i];
            double acc = 0.0;
            for (int c = 0; c < CCH; c++) {
                float as = g_S2[(b*(CCH+1) + c)*NN + i] / nrm;
                acc += (double)fabsf(g_prob[(b*CCH + c)*NN + i] - as);
            }
            l = acc * (double)r;
        }
    }
    sl[threadIdx.x] = l; sn[threadIdx.x] = n;
    __syncthreads();
    for (int o = 128; o; o >>= 1) {
        if (threadIdx.x < o) { sl[threadIdx.x] += sl[threadIdx.x+o]; sn[threadIdx.x] += sn[threadIdx.x+o]; }
        __syncthreads();
    }
    if (threadIdx.x == 0) { atomicAdd(&g_acc[0], sl[0]); atomicAdd(&g_acc[1], sn[0]); }
}

__global__ void k_fin(float* out) {
    if (threadIdx.x == 0)
        out[0] = (g_acc[1] > 0.0) ? (float)(g_acc[0]/g_acc[1]) : 0.0f;
}

// ---------------- launch ----------------
extern "C" void kernel_launch(void* const* d_in, const int* in_sizes, int n_in,
                              void* d_out, int out_size) {
    const float* preds = (const float*)d_in[0];
    const float* lf    = (const float*)d_in[1];
    const float* hf    = (const float*)d_in[2];
    const float* roi   = (const float*)d_in[3];
    float* out = (float*)d_out;

    const int smem_boruvka = NN*8 + 3*NN*4;               // 184320
    const int smem_bfs     = NN*4*4 + 2*NN*4 + 256;       // 221440
    const int smem_hld     = 5*NN*4 + (NN+4)*4;           // 221200
    const int smem_filter  = 4*NN*4 + 2*MAXCH*4;          // 212992
    cudaFuncSetAttribute(k_boruvka, cudaFuncAttributeMaxDynamicSharedMemorySize, smem_boruvka);
    cudaFuncSetAttribute(k_bfs,     cudaFuncAttributeMaxDynamicSharedMemorySize, smem_bfs);
    cudaFuncSetAttribute(k_hld,     cudaFuncAttributeMaxDynamicSharedMemorySize, smem_hld);
    cudaFuncSetAttribute(k_filter,  cudaFuncAttributeMaxDynamicSharedMemorySize, smem_filter);

    k_sigmoid<<<(BN*CCH*NN + 255)/256, 256>>>(preds);
    k_ew_high<<<(BN*NCHUNK*NE + 255)/256, 256>>>(hf);
    k_ew_red <<<(BN*NE + 255)/256, 256>>>(lf);
    k_boruvka<<<NTREE, 1024, smem_boruvka>>>();   // profiled launch (idx 3)
    k_bfs    <<<NTREE, 256, smem_bfs>>>();
    k_hld    <<<NTREE, 512, smem_hld>>>();
    {
        dim3 g1(BN, CCH+1);
        k_filter<<<g1, 256, smem_filter>>>(0, 0, 0);
        k_filter<<<g1, 256, smem_filter>>>(1, 1, 1);
    }
    k_loss   <<<(BN*NN + 255)/256, 256>>>(roi);
    k_fin    <<<1, 32>>>(out);
}

// round 8
// speedup vs baseline: 1.4799x; 1.4799x over previous
#include <cuda_runtime.h>
#include <math.h>

#define BN 4
#define CCH 21
#define HH 96
#define WW 96
#define NN (HH*WW)          // 9216
#define NEH (HH*(WW-1))     // 9120
#define NEV ((HH-1)*WW)     // 9120
#define NE  (NEH+NEV)       // 18240
#define NTREE 8             // s = b*2 + t, t=0 low, t=1 high
#define NCHUNK 32
#define CHSZ  16            // 512 / NCHUNK
#define ROOT  (48*WW + 48)  // center root: two-pass tree filter is root-invariant

// ---------------- scratch ----------------
__device__ double g_ws[NTREE*NE];
__device__ unsigned long long g_key[NTREE*NE];
__device__ double g_part[BN*NCHUNK*NE];
__device__ int    g_adj[NTREE*NN*4];
__device__ int    g_ord[NTREE*NN];     // node at BFS position
__device__ int    g_pp[NTREE*NN];      // parent BFS position
__device__ int    g_loff[NTREE*(NN+4)];
__device__ int    g_nlev[NTREE];
__device__ float  g_w[NTREE*NN];       // weight, BFS-position-indexed
__device__ float  g_prob[BN*CCH*NN];
__device__ float  g_S[BN*(CCH+1)*NN];
__device__ float  g_S2[BN*(CCH+1)*NN];
__device__ double g_acc[2];

__device__ __forceinline__ void edge_nodes(int e, int &a, int &b) {
    if (e < NEH) { int r = e / (WW-1); int c = e - r*(WW-1); a = r*WW + c; b = a + 1; }
    else         { a = e - NEH; b = a + WW; }
}

__device__ __forceinline__ unsigned long long pack_key(double w, int e) {
    unsigned long long kb = (unsigned long long)__double_as_longlong(w);
    return (kb & ~32767ull) | (unsigned long long)e;
}

__device__ __forceinline__ void two_sum(float a, float b, float &s, float &e) {
    s = __fadd_rn(a, b);
    float bp = __fsub_rn(s, a);
    e = __fadd_rn(__fsub_rn(a, __fsub_rn(s, bp)), __fsub_rn(b, bp));
}

// ---------------- kernels ----------------
__global__ void k_sigmoid(const float* __restrict__ preds) {
    int i = blockIdx.x*blockDim.x + threadIdx.x;
    if (i < 2) g_acc[i] = 0.0;
    if (i < BN*CCH*NN) g_prob[i] = 1.0f/(1.0f + expf(-preds[i]));
}

// df64 (float-float) squared distance on the fp32 pipe; per-chunk partials.
__global__ void k_ew_high(const float* __restrict__ hf) {
    int idx = blockIdx.x*blockDim.x + threadIdx.x;
    if (idx >= BN*NCHUNK*NE) return;
    int b = idx / (NCHUNK*NE);
    int r = idx - b*(NCHUNK*NE);
    int ch = r / NE, e = r - ch*NE;
    int a, bb; edge_nodes(e, a, bb);
    const float* f = hf + b*512*NN + ch*CHSZ*NN;
    float sh = 0.0f, sl = 0.0f;
    #pragma unroll
    for (int c = 0; c < CHSZ; c++) {
        float av = f[c*NN+a], bv = f[c*NN+bb];
        float dh, dl; two_sum(av, -bv, dh, dl);
        float p  = __fmul_rn(dh, dh);
        float pe = __fmaf_rn(dh, dh, -p);
        pe = __fmaf_rn(__fmul_rn(2.0f, dh), dl, pe);
        float t, er; two_sum(sh, p, t, er);
        sl = __fadd_rn(sl, __fadd_rn(er, pe));
        sh = t;
    }
    g_part[(b*NCHUNK + ch)*NE + e] = (double)sh + (double)sl;
}

// low-tree edge weights (f64) + fixed-order reduction of high-tree partials
__global__ void k_ew_red(const float* __restrict__ lf) {
    int idx = blockIdx.x*blockDim.x + threadIdx.x;
    if (idx >= BN*NE) return;
    int b = idx / NE, e = idx - b*NE;
    int a, bb; edge_nodes(e, a, bb);
    const float* f = lf + b*3*NN;
    double accl = 0.0;
    #pragma unroll
    for (int c = 0; c < 3; c++) {
        double d = (double)f[c*NN+a] - (double)f[c*NN+bb];
        accl += d*d;
    }
    g_ws[(b*2)*NE + e] = accl;
    g_key[(b*2)*NE + e] = pack_key(accl, e);
    double acc = 0.0;
    #pragma unroll 8
    for (int ch = 0; ch < NCHUNK; ch++) acc += g_part[(b*NCHUNK + ch)*NE + e];
    g_ws[(b*2+1)*NE + e] = acc;
    g_key[(b*2+1)*NE + e] = pack_key(acc, e);
}

// Parallel Boruvka, one block per tree; fused min/argmin via packed key;
// test-before-atomic; deg in smem.
__global__ void __launch_bounds__(1024) k_boruvka() {
    extern __shared__ unsigned long long sh_u[];
    unsigned long long* minw = sh_u;       // NN
    int* parent = (int*)(minw + NN);       // NN
    int* hook   = parent + NN;             // NN
    int* deg    = hook + NN;               // NN
    __shared__ int total, flag;
    int s = blockIdx.x;
    const unsigned long long* key = g_key + s*NE;
    int* adj = g_adj + s*NN*4;
    for (int i = threadIdx.x; i < NN; i += blockDim.x) { parent[i] = i; deg[i] = 0; }
    for (int i = threadIdx.x; i < NN*4; i += blockDim.x) adj[i] = -1;
    if (threadIdx.x == 0) total = 0;
    __syncthreads();
    for (int round = 0; round < 24; round++) {
        for (int i = threadIdx.x; i < NN; i += blockDim.x) {
            minw[i] = 0xFFFFFFFFFFFFFFFFull; hook[i] = -1;
        }
        __syncthreads();
        for (int e = threadIdx.x; e < NE; e += blockDim.x) {
            int a, b; edge_nodes(e, a, b);
            int ra = parent[a], rb = parent[b];
            if (ra != rb) {
                unsigned long long k = key[e];
                if (k < minw[ra]) atomicMin(&minw[ra], k);
                if (k < minw[rb]) atomicMin(&minw[rb], k);
            }
        }
        __syncthreads();
        for (int i = threadIdx.x; i < NN; i += blockDim.x) {
            unsigned long long mk = minw[i];
            if (parent[i] == i && mk != 0xFFFFFFFFFFFFFFFFull) {
                int e = (int)(mk & 32767ull);
                int a, b; edge_nodes(e, a, b);
                int ra = parent[a], rb = parent[b];
                int other = (ra == i) ? rb : ra;
                bool mutual = (minw[other] == mk);
                if (!mutual || i < other) {
                    int da = atomicAdd(&deg[a], 1); adj[a*4+da] = b;
                    int db = atomicAdd(&deg[b], 1); adj[b*4+db] = a;
                    atomicAdd(&total, 1);
                    hook[i] = other;
                }
            }
        }
        __syncthreads();
        for (int i = threadIdx.x; i < NN; i += blockDim.x) {
            int t = hook[i];
            if (t >= 0) parent[i] = t;
        }
        __syncthreads();
        for (;;) {
            if (threadIdx.x == 0) flag = 0;
            __syncthreads();
            for (int i = threadIdx.x; i < NN; i += blockDim.x) {
                int p = parent[i], gp = parent[p];
                if (p != gp) { parent[i] = gp; flag = 1; }
            }
            __syncthreads();
            int f = flag;
            __syncthreads();
            if (!f) break;
        }
        if (total >= NN-1) break;
    }
}

// Single-warp BFS from ROOT (center). Emits order, parent positions, level
// offsets; tail computes position-indexed weights.
__global__ void __launch_bounds__(256) k_bfs() {
    extern __shared__ int sh[];
    int* adj_s = sh;            // NN*4
    int* ord   = adj_s + NN*4;  // NN
    int* pp    = ord + NN;      // NN
    int* cnts  = pp + NN;       // 64 rotating counters
    int s = blockIdx.x;
    const int* adj = g_adj + s*NN*4;
    int* loff = g_loff + s*(NN+4);
    for (int i = threadIdx.x; i < NN*4; i += blockDim.x) adj_s[i] = adj[i];
    for (int i = threadIdx.x; i < 64; i += blockDim.x) cnts[i] = 0;
    if (threadIdx.x == 0) { ord[0] = ROOT; pp[0] = 0; loff[0] = 0; loff[1] = 1; }
    __syncthreads();
    if (threadIdx.x < 32) {
        int lane = threadIdx.x;
        int cur = 0, curEnd = 1, lvl = 0;
        for (;;) {
            int slot = lvl & 63;
            for (int q = cur + lane; q < curEnd; q += 32) {
                int u = ord[q];
                int pu = (q == 0) ? -1 : ord[pp[q]];
                #pragma unroll
                for (int j = 0; j < 4; j++) {
                    int v = adj_s[u*4 + j];
                    if (v >= 0 && v != pu) {
                        int pos = atomicAdd(&cnts[slot], 1);
                        ord[curEnd + pos] = v;
                        pp[curEnd + pos] = q;
                    }
                }
            }
            __syncwarp();
            int c = cnts[slot];
            __syncwarp();
            if (lane == 0) cnts[slot] = 0;   // reused 64 levels later; safe
            if (c == 0) break;
            lvl++;
            if (lane == 0) loff[lvl+1] = curEnd + c;
            cur = curEnd; curEnd += c;
        }
        if (lane == 0) g_nlev[s] = lvl + 1;
    }
    __syncthreads();
    float sig = (s & 1) ? 1.0f : 0.02f;
    for (int k = threadIdx.x; k < NN; k += blockDim.x) {
        g_ord[s*NN + k] = ord[k];
        g_pp[s*NN + k]  = pp[k];
        if (k == 0) { g_w[s*NN] = 0.0f; continue; }
        int v = ord[k];
        int u = ord[pp[k]];
        int e;
        if      (u == v-1)  { int r2 = v/WW, c2 = v%WW; e = r2*(WW-1) + (c2-1); }
        else if (u == v+1)  { int r2 = v/WW, c2 = v%WW; e = r2*(WW-1) + c2; }
        else if (u == v-WW) { e = NEH + (v-WW); }
        else                { e = NEH + v; }
        g_w[s*NN + k] = expf(-(float)g_ws[s*NE + e] / sig);
    }
}

// Two-pass tree DP in BFS-position space: levels are contiguous ranges,
// parent access via pp[] only. One block per (batch, channel).
__global__ void __launch_bounds__(256) k_filter(int t, int srcsel, int dst) {
    extern __shared__ float shf[];
    float* A = shf;               // NN  (position-indexed)
    float* S = A + NN;            // NN
    float* w = S + NN;            // NN
    int* pp    = (int*)(w + NN);  // NN
    int* ord   = pp + NN;         // NN
    int* loffs = ord + NN;        // NN+4
    int b = blockIdx.x, c = blockIdx.y;
    int s = b*2 + t;
    int nl = g_nlev[s];
    const float* s1c = g_S + (b*(CCH+1) + c)*NN;
    const float* s1n = g_S + (b*(CCH+1) + CCH)*NN;
    for (int i = threadIdx.x; i < NN; i += blockDim.x) {
        int node = g_ord[s*NN + i];
        float v;
        if (c == CCH)           v = 1.0f;
        else if (srcsel == 0)   v = g_prob[(b*CCH + c)*NN + node];
        else                    v = s1c[node] / s1n[node];
        A[i]   = v;
        w[i]   = g_w[s*NN + i];
        pp[i]  = g_pp[s*NN + i];
        ord[i] = node;
    }
    for (int i = threadIdx.x; i <= nl; i += blockDim.x) loffs[i] = g_loff[s*(NN+4) + i];
    __syncthreads();
    int tid = threadIdx.x;
    // up: leaves -> root
    for (int d = nl - 1; d >= 1; d--) {
        int s0 = loffs[d], cnt2 = loffs[d+1] - s0;
        if (cnt2 <= 32) {
            if (tid < 32) {
                if (tid < cnt2) {
                    int k = s0 + tid;
                    atomicAdd(&A[pp[k]], w[k]*A[k]);
                }
                __syncwarp();
            }
        } else {
            __syncthreads();
            for (int k = s0 + tid; k < s0 + cnt2; k += blockDim.x)
                atomicAdd(&A[pp[k]], w[k]*A[k]);
            __syncthreads();
        }
    }
    __syncthreads();
    if (tid == 0) S[0] = A[0];
    __syncthreads();
    // down: root -> leaves
    for (int d = 1; d < nl; d++) {
        int s0 = loffs[d], cnt2 = loffs[d+1] - s0;
        if (cnt2 <= 32) {
            if (tid < 32) {
                if (tid < cnt2) {
                    int k = s0 + tid;
                    float wv = w[k], av = A[k];
                    S[k] = av + wv*(S[pp[k]] - wv*av);
                }
                __syncwarp();
            }
        } else {
            __syncthreads();
            for (int k = s0 + tid; k < s0 + cnt2; k += blockDim.x) {
                float wv = w[k], av = A[k];
                S[k] = av + wv*(S[pp[k]] - wv*av);
            }
            __syncthreads();
        }
    }
    __syncthreads();
    float* outS = ((dst == 0) ? g_S : g_S2) + (b*(CCH+1) + c)*NN;
    for (int i = threadIdx.x; i < NN; i += blockDim.x) outS[ord[i]] = S[i];
}

__global__ void k_loss(const float* __restrict__ roi) {
    __shared__ double sl[256], sn[256];
    int idx = blockIdx.x*blockDim.x + threadIdx.x;
    double l = 0.0, n = 0.0;
    if (idx < BN*NN) {
        int b = idx / NN, i = idx - b*NN;
        int h = i / WW, w = i - h*WW;
        float r = roi[b*(2*HH)*(2*WW) + (2*h)*(2*WW) + 2*w];
        n = (double)r;
        if (r != 0.0f) {
            float nrm = g_S2[(b*(CCH+1) + CCH)*NN + i];
            double acc = 0.0;
            for (int c = 0; c < CCH; c++) {
                float as = g_S2[(b*(CCH+1) + c)*NN + i] / nrm;
                acc += (double)fabsf(g_prob[(b*CCH + c)*NN + i] - as);
            }
            l = acc * (double)r;
        }
    }
    sl[threadIdx.x] = l; sn[threadIdx.x] = n;
    __syncthreads();
    for (int o = 128; o; o >>= 1) {
        if (threadIdx.x < o) { sl[threadIdx.x] += sl[threadIdx.x+o]; sn[threadIdx.x] += sn[threadIdx.x+o]; }
        __syncthreads();
    }
    if (threadIdx.x == 0) { atomicAdd(&g_acc[0], sl[0]); atomicAdd(&g_acc[1], sn[0]); }
}

__global__ void k_fin(float* out) {
    if (threadIdx.x == 0)
        out[0] = (g_acc[1] > 0.0) ? (float)(g_acc[0]/g_acc[1]) : 0.0f;
}

// ---------------- launch ----------------
extern "C" void kernel_launch(void* const* d_in, const int* in_sizes, int n_in,
                              void* d_out, int out_size) {
    const float* preds = (const float*)d_in[0];
    const float* lf    = (const float*)d_in[1];
    const float* hf    = (const float*)d_in[2];
    const float* roi   = (const float*)d_in[3];
    float* out = (float*)d_out;

    const int smem_boruvka = NN*8 + 3*NN*4;          // 184320
    const int smem_bfs     = NN*4*4 + 2*NN*4 + 256;  // 221440
    const int smem_filter  = 5*NN*4 + (NN+4)*4;      // 221200
    cudaFuncSetAttribute(k_boruvka, cudaFuncAttributeMaxDynamicSharedMemorySize, smem_boruvka);
    cudaFuncSetAttribute(k_bfs,     cudaFuncAttributeMaxDynamicSharedMemorySize, smem_bfs);
    cudaFuncSetAttribute(k_filter,  cudaFuncAttributeMaxDynamicSharedMemorySize, smem_filter);

    k_sigmoid<<<(BN*CCH*NN + 255)/256, 256>>>(preds);
    k_ew_high<<<(BN*NCHUNK*NE + 255)/256, 256>>>(hf);
    k_ew_red <<<(BN*NE + 255)/256, 256>>>(lf);
    k_boruvka<<<NTREE, 1024, smem_boruvka>>>();
    k_bfs    <<<NTREE, 256, smem_bfs>>>();
    {
        dim3 g1(BN, CCH+1);
        k_filter<<<g1, 256, smem_filter>>>(0, 0, 0);
        k_filter<<<g1, 256, smem_filter>>>(1, 1, 1);
    }
    k_loss   <<<(BN*NN + 255)/256, 256>>>(roi);
    k_fin    <<<1, 32>>>(out);
}